// round 2
// baseline (speedup 1.0000x reference)
#include <cuda_runtime.h>
#include <math.h>

// Problem constants
#define BB   16
#define HH   128
#define WW   128
#define HWSZ (HH*WW)          // 16384
#define CSP  63               // space channels
#define CIN1 32
#define CIN2 64

// Scratch (device globals; no runtime allocation allowed)
__device__ float g_s1[BB*CSP*HWSZ];   // conv1 output
__device__ float g_y1[BB*64*HWSZ];    // projected relu(bn1)
__device__ float g_s2[BB*CSP*HWSZ];   // conv2 output
__device__ float g_sp[BB*CSP*HWSZ];   // 1x1 conv output
// per-conv BN partials: [4 groups][256 blocks][16 oc][2]
#define PART_STRIDE (4*256*16*2)
__device__ float g_part[3*PART_STRIDE];
// per-conv folded BN coeffs: [63][2] = {a, b} with h = a*s + b
__device__ float g_stats[3*CSP*2];

// ---------------------------------------------------------------------------
// Direct conv: 32x32 output tile per block, 256 threads, 4 pixels/thread,
// 16 output channels per block (grid.z = B * 4 groups).
// Also emits deterministic per-block BN partial sums (sum, sumsq).
// ---------------------------------------------------------------------------
template<int KS, int CIN>
__global__ __launch_bounds__(256, 2)
void conv_k(const float* __restrict__ in, const float* __restrict__ w,
            const float* __restrict__ bias, float* __restrict__ out,
            float* __restrict__ part)
{
    constexpr int TS   = 32;
    constexpr int HALO = (KS == 3) ? 1 : 0;
    constexpr int IT   = TS + 2*HALO;           // 34 or 32
    constexpr int KK   = KS*KS;

    __shared__ float tile[IT*IT];
    __shared__ float wsh[16*KK];
    __shared__ float redw[8][16][2];

    const int t   = threadIdx.x;
    const int tx  = t & 31;
    const int ty0 = t >> 5;                      // 0..7
    const int wid = t >> 5;
    const int bz  = blockIdx.z;
    const int b   = bz >> 2;
    const int grp = bz & 3;
    const int oc0 = grp * 16;
    const int nOC = (oc0 + 16 <= CSP) ? 16 : (CSP - oc0);   // 16 or 15
    const int x0  = blockIdx.x * TS;
    const int y0  = blockIdx.y * TS;

    float acc[16][4];
#pragma unroll
    for (int o = 0; o < 16; o++)
#pragma unroll
        for (int k = 0; k < 4; k++) acc[o][k] = 0.f;

    for (int ic = 0; ic < CIN; ic++) {
        __syncthreads();
        // load input tile (with halo / zero pad)
        const float* ip = in + (size_t)(b*CIN + ic) * HWSZ;
        for (int i = t; i < IT*IT; i += 256) {
            int r = i / IT, c = i - r*IT;
            int gy = y0 + r - HALO, gx = x0 + c - HALO;
            float v = 0.f;
            if (gy >= 0 && gy < HH && gx >= 0 && gx < WW) v = ip[gy*WW + gx];
            tile[i] = v;
        }
        // load weights for this (group, ic)
        for (int i = t; i < 16*KK; i += 256) {
            int oc = i / KK, k = i - oc*KK;
            float v = 0.f;
            if (oc0 + oc < CSP) v = w[((size_t)(oc0+oc)*CIN + ic)*KK + k];
            wsh[i] = v;
        }
        __syncthreads();

        // gather this thread's inputs for 4 pixels
        float iv[4][KK];
#pragma unroll
        for (int k = 0; k < 4; k++) {
            int yy = ty0 + 8*k;
            if (KS == 3) {
#pragma unroll
                for (int dy = 0; dy < 3; dy++)
#pragma unroll
                    for (int dx = 0; dx < 3; dx++)
                        iv[k][dy*3+dx] = tile[(yy+dy)*IT + tx + dx];
            } else {
                iv[k][0] = tile[yy*IT + tx];
            }
        }
        // accumulate
#pragma unroll
        for (int oc = 0; oc < 16; oc++) {
            float wr[KK];
#pragma unroll
            for (int j = 0; j < KK; j++) wr[j] = wsh[oc*KK + j];
#pragma unroll
            for (int k = 0; k < 4; k++)
#pragma unroll
                for (int j = 0; j < KK; j++)
                    acc[oc][k] = fmaf(iv[k][j], wr[j], acc[oc][k]);
        }
    }

    // epilogue: bias, store, deterministic BN partials
#pragma unroll
    for (int oc = 0; oc < 16; oc++) {
        float bv = (oc < nOC) ? bias[oc0 + oc] : 0.f;
        float s = 0.f, q = 0.f;
        float* op = out + (size_t)(b*CSP + oc0 + oc) * HWSZ;
#pragma unroll
        for (int k = 0; k < 4; k++) {
            float v = acc[oc][k] + bv;
            if (oc < nOC) op[(y0 + ty0 + 8*k)*WW + x0 + tx] = v;
            s += v;
            q += v*v;
        }
        // warp tree reduce (deterministic)
#pragma unroll
        for (int off = 16; off > 0; off >>= 1) {
            s += __shfl_down_sync(0xffffffffu, s, off);
            q += __shfl_down_sync(0xffffffffu, q, off);
        }
        if ((t & 31) == 0) { redw[wid][oc][0] = s; redw[wid][oc][1] = q; }
    }
    __syncthreads();
    if (t < 32) {
        int oc = t >> 1, which = t & 1;
        float s = 0.f;
#pragma unroll
        for (int wgi = 0; wgi < 8; wgi++) s += redw[wgi][oc][which];
        int blkIdx = b*16 + blockIdx.y*4 + blockIdx.x;          // 0..255
        part[((grp*256 + blkIdx)*16 + oc)*2 + which] = s;
    }
}

// ---------------------------------------------------------------------------
// Finalize BN stats: fold gamma/beta into (a, b): h = a*s + b
// ---------------------------------------------------------------------------
__global__ void stats_k(const float* __restrict__ part,
                        const float* __restrict__ gamma,
                        const float* __restrict__ beta,
                        float* __restrict__ stats)
{
    int c = threadIdx.x;
    if (c >= CSP) return;
    int grp = c >> 4, oc = c & 15;
    double s = 0.0, q = 0.0;
    for (int blk = 0; blk < 256; blk++) {
        const float* p = part + ((size_t)(grp*256 + blk)*16 + oc)*2;
        s += (double)p[0];
        q += (double)p[1];
    }
    const double n = (double)BB * (double)HWSZ;
    double mu  = s / n;
    double var = q / n - mu*mu;
    float rstd = (float)(1.0 / sqrt(var + 1e-5));
    float a  = gamma[c] * rstd;
    float bc = beta[c] - a * (float)mu;
    stats[c*2]   = a;
    stats[c*2+1] = bc;
}

// ---------------------------------------------------------------------------
// bn1 + relu + Lorentz project -> y1 (64ch, time channel first)
// ---------------------------------------------------------------------------
__global__ __launch_bounds__(256)
void bnrp_k(const float* __restrict__ s1, const float* __restrict__ stats,
            float* __restrict__ y1)
{
    __shared__ float a[CSP], bc[CSP];
    int t = threadIdx.x;
    if (t < CSP) { a[t] = stats[2*t]; bc[t] = stats[2*t+1]; }
    __syncthreads();
    int g = blockIdx.x * 256 + t;           // 0 .. B*HW-1
    int b = g >> 14, pix = g & (HWSZ - 1);
    const float* sp_ = s1 + (size_t)b*CSP*HWSZ + pix;
    float* yp = y1 + (size_t)b*64*HWSZ + pix;
    float q = 0.f;
#pragma unroll 9
    for (int c = 0; c < CSP; c++) {
        float v = sp_[(size_t)c*HWSZ];
        float h = fmaf(a[c], v, bc[c]);
        float r = fmaxf(h, 0.f);
        yp[(size_t)(c+1)*HWSZ] = r;
        q = fmaf(r, r, q);
    }
    yp[0] = sqrtf(1.f + q);
}

// ---------------------------------------------------------------------------
// Final: bn2(s2) + bnp(sp), relu, project -> out (64ch)
// ---------------------------------------------------------------------------
__global__ __launch_bounds__(256)
void final_k(const float* __restrict__ s2, const float* __restrict__ sp,
             const float* __restrict__ st2, const float* __restrict__ stp,
             float* __restrict__ out)
{
    __shared__ float a2[CSP], b2s[CSP], apv[CSP], bpv[CSP];
    int t = threadIdx.x;
    if (t < CSP) {
        a2[t]  = st2[2*t]; b2s[t] = st2[2*t+1];
        apv[t] = stp[2*t]; bpv[t] = stp[2*t+1];
    }
    __syncthreads();
    int g = blockIdx.x * 256 + t;
    int b = g >> 14, pix = g & (HWSZ - 1);
    const float* p2 = s2 + (size_t)b*CSP*HWSZ + pix;
    const float* pp = sp + (size_t)b*CSP*HWSZ + pix;
    float* op = out + (size_t)b*64*HWSZ + pix;
    float q = 0.f;
#pragma unroll 9
    for (int c = 0; c < CSP; c++) {
        float v2 = p2[(size_t)c*HWSZ];
        float vp = pp[(size_t)c*HWSZ];
        float h = fmaf(a2[c], v2, b2s[c]) + fmaf(apv[c], vp, bpv[c]);
        float r = fmaxf(h, 0.f);
        op[(size_t)(c+1)*HWSZ] = r;
        q = fmaf(r, r, q);
    }
    op[0] = sqrtf(1.f + q);
}

// ---------------------------------------------------------------------------
extern "C" void kernel_launch(void* const* d_in, const int* in_sizes, int n_in,
                              void* d_out, int out_size)
{
    const float* x   = (const float*)d_in[0];
    const float* w1  = (const float*)d_in[1];
    const float* b1  = (const float*)d_in[2];
    const float* g1  = (const float*)d_in[3];
    const float* bt1 = (const float*)d_in[4];
    const float* w2  = (const float*)d_in[5];
    const float* b2  = (const float*)d_in[6];
    const float* g2  = (const float*)d_in[7];
    const float* bt2 = (const float*)d_in[8];
    const float* wp  = (const float*)d_in[9];
    const float* bp  = (const float*)d_in[10];
    const float* gp  = (const float*)d_in[11];
    const float* btp = (const float*)d_in[12];
    float* out = (float*)d_out;

    void *p_s1, *p_y1, *p_s2, *p_sp, *p_part, *p_stats;
    cudaGetSymbolAddress(&p_s1, g_s1);
    cudaGetSymbolAddress(&p_y1, g_y1);
    cudaGetSymbolAddress(&p_s2, g_s2);
    cudaGetSymbolAddress(&p_sp, g_sp);
    cudaGetSymbolAddress(&p_part, g_part);
    cudaGetSymbolAddress(&p_stats, g_stats);
    float* s1 = (float*)p_s1;
    float* y1 = (float*)p_y1;
    float* s2 = (float*)p_s2;
    float* sp = (float*)p_sp;
    float* part  = (float*)p_part;
    float* stats = (float*)p_stats;

    dim3 cg(4, 4, BB*4);
    const int ew_blocks = BB*HWSZ/256;   // 1024

    // stage 1: conv1 + BN1 stats
    conv_k<3, CIN1><<<cg, 256>>>(x, w1, b1, s1, part + 0*PART_STRIDE);
    stats_k<<<1, 64>>>(part + 0*PART_STRIDE, g1, bt1, stats + 0*CSP*2);
    bnrp_k<<<ew_blocks, 256>>>(s1, stats + 0*CSP*2, y1);

    // stage 2: conv2 (on 64ch projected) and 1x1 shortcut, + stats
    conv_k<3, CIN2><<<cg, 256>>>(y1, w2, b2, s2, part + 1*PART_STRIDE);
    conv_k<1, CIN1><<<cg, 256>>>(x, wp, bp, sp, part + 2*PART_STRIDE);
    stats_k<<<1, 64>>>(part + 1*PART_STRIDE, g2, bt2, stats + 1*CSP*2);
    stats_k<<<1, 64>>>(part + 2*PART_STRIDE, gp, btp, stats + 2*CSP*2);

    // stage 3: merge, relu, project
    final_k<<<ew_blocks, 256>>>(s2, sp, stats + 1*CSP*2, stats + 2*CSP*2, out);
}

// round 3
// speedup vs baseline: 1.5559x; 1.5559x over previous
#include <cuda_runtime.h>
#include <math.h>

#define BB   16
#define HH   128
#define WW   128
#define HWSZ (HH*WW)
#define CSP  63
#define CIN1 32
#define CIN2 64

__device__ float g_s1[BB*CSP*HWSZ];
__device__ float g_y1[BB*64*HWSZ];
__device__ float g_s2[BB*CSP*HWSZ];
__device__ float g_sp[BB*CSP*HWSZ];
#define PART_STRIDE (4*256*16*2)
__device__ float g_part[3*PART_STRIDE];
__device__ float g_stats[3*CSP*2];

// ---------------------------------------------------------------------------
// Direct conv, v2: 32x32 tile, 256 threads, each thread 4 CONTIGUOUS rows x
// 16 oc. 2 input channels per smem stage. Vectorized weight LDS.
// ---------------------------------------------------------------------------
template<int KS, int CIN>
__global__ __launch_bounds__(256, 2)
void conv_k(const float* __restrict__ in, const float* __restrict__ w,
            const float* __restrict__ bias, float* __restrict__ out,
            float* __restrict__ part)
{
    constexpr int TS    = 32;
    constexpr int HALO  = (KS == 3) ? 1 : 0;
    constexpr int IT    = TS + 2*HALO;          // 34 or 32
    constexpr int KK    = KS*KS;                // 9 or 1
    constexpr int WPAD  = (KS == 3) ? 12 : 1;   // padded weight stride (floats)
    constexpr int ROWS  = 4 + 2*HALO;           // 6 or 4

    __shared__ __align__(16) float tile[2][IT*IT];
    __shared__ __align__(16) float wsh[2][16*WPAD];
    __shared__ float redw[8][16][2];

    const int t   = threadIdx.x;
    const int tx  = t & 31;
    const int ty  = t >> 5;                     // 0..7 -> rows ty*4 .. ty*4+3
    const int bz  = blockIdx.z;
    const int b   = bz >> 2;
    const int grp = bz & 3;
    const int oc0 = grp * 16;
    const int nOC = (oc0 + 16 <= CSP) ? 16 : (CSP - oc0);
    const int x0  = blockIdx.x * TS;
    const int y0  = blockIdx.y * TS;

    float acc[16][4];
#pragma unroll
    for (int o = 0; o < 16; o++)
#pragma unroll
        for (int k = 0; k < 4; k++) acc[o][k] = 0.f;

    for (int st = 0; st < CIN/2; st++) {
        const int ic0 = st*2;
        __syncthreads();
        // load 2 input-channel tiles (shared geometry / predicate)
        const float* ip0 = in + (size_t)(b*CIN + ic0) * HWSZ;
        const float* ip1 = ip0 + HWSZ;
        for (int i = t; i < IT*IT; i += 256) {
            int r = i / IT, c = i - r*IT;
            int gy = y0 + r - HALO, gx = x0 + c - HALO;
            bool ok = (gy >= 0 && gy < HH && gx >= 0 && gx < WW);
            int off = gy*WW + gx;
            tile[0][i] = ok ? ip0[off] : 0.f;
            tile[1][i] = ok ? ip1[off] : 0.f;
        }
        // load weights for 2 channels, padded stride
        for (int i = t; i < 2*16*KK; i += 256) {
            int cc  = i / (16*KK);
            int rem = i - cc*(16*KK);
            int oc  = rem / KK;
            int k   = rem - oc*KK;
            float v = 0.f;
            if (oc0 + oc < CSP)
                v = w[((size_t)(oc0+oc)*CIN + ic0 + cc)*KK + k];
            wsh[cc][oc*WPAD + k] = v;
        }
        __syncthreads();

#pragma unroll
        for (int cc = 0; cc < 2; cc++) {
            // gather: ROWS x KS window covering this thread's 4 rows
            float iv[ROWS][KS];
#pragma unroll
            for (int r = 0; r < ROWS; r++)
#pragma unroll
                for (int dx = 0; dx < KS; dx++)
                    iv[r][dx] = tile[cc][(ty*4 + r)*IT + tx + dx];

#pragma unroll
            for (int oc = 0; oc < 16; oc++) {
                if (KS == 3) {
                    const float4 w0 = *reinterpret_cast<const float4*>(&wsh[cc][oc*WPAD]);
                    const float4 w1 = *reinterpret_cast<const float4*>(&wsh[cc][oc*WPAD+4]);
                    const float  w8 = wsh[cc][oc*WPAD+8];
                    float wr[9] = {w0.x, w0.y, w0.z, w0.w, w1.x, w1.y, w1.z, w1.w, w8};
#pragma unroll
                    for (int k = 0; k < 4; k++)
#pragma unroll
                        for (int dy = 0; dy < 3; dy++)
#pragma unroll
                            for (int dx = 0; dx < 3; dx++)
                                acc[oc][k] = fmaf(iv[k+dy][dx], wr[dy*3+dx], acc[oc][k]);
                } else {
                    const float wv = wsh[cc][oc];
#pragma unroll
                    for (int k = 0; k < 4; k++)
                        acc[oc][k] = fmaf(iv[k][0], wv, acc[oc][k]);
                }
            }
        }
    }

    // epilogue: bias, store, deterministic BN partials
#pragma unroll
    for (int oc = 0; oc < 16; oc++) {
        float bv = (oc < nOC) ? bias[oc0 + oc] : 0.f;
        float s = 0.f, q = 0.f;
        float* op = out + (size_t)(b*CSP + oc0 + oc) * HWSZ;
#pragma unroll
        for (int k = 0; k < 4; k++) {
            float v = acc[oc][k] + bv;
            if (oc < nOC) op[(y0 + ty*4 + k)*WW + x0 + tx] = v;
            s += v;
            q += v*v;
        }
#pragma unroll
        for (int off = 16; off > 0; off >>= 1) {
            s += __shfl_down_sync(0xffffffffu, s, off);
            q += __shfl_down_sync(0xffffffffu, q, off);
        }
        if (tx == 0) { redw[ty][oc][0] = s; redw[ty][oc][1] = q; }
    }
    __syncthreads();
    if (t < 32) {
        int oc = t >> 1, which = t & 1;
        float s = 0.f;
#pragma unroll
        for (int wgi = 0; wgi < 8; wgi++) s += redw[wgi][oc][which];
        int blkIdx = b*16 + blockIdx.y*4 + blockIdx.x;
        part[((grp*256 + blkIdx)*16 + oc)*2 + which] = s;
    }
}

// ---------------------------------------------------------------------------
// Parallel BN finalize: one block per channel, 256 threads, tree reduce.
// ---------------------------------------------------------------------------
__global__ __launch_bounds__(256)
void stats_k(const float* __restrict__ part,
             const float* __restrict__ gamma,
             const float* __restrict__ beta,
             float* __restrict__ stats)
{
    __shared__ double ss[256], qq[256];
    const int c = blockIdx.x;                 // 0..62
    const int t = threadIdx.x;                // one partial block each
    const int grp = c >> 4, oc = c & 15;
    const float* p = part + ((size_t)(grp*256 + t)*16 + oc)*2;
    ss[t] = (double)p[0];
    qq[t] = (double)p[1];
#pragma unroll
    for (int off = 128; off > 0; off >>= 1) {
        __syncthreads();
        if (t < off) { ss[t] += ss[t+off]; qq[t] += qq[t+off]; }
    }
    if (t == 0) {
        const double n = (double)BB * (double)HWSZ;
        double mu  = ss[0] / n;
        double var = qq[0] / n - mu*mu;
        float rstd = (float)(1.0 / sqrt(var + 1e-5));
        float a  = gamma[c] * rstd;
        float bc = beta[c] - a * (float)mu;
        stats[c*2]   = a;
        stats[c*2+1] = bc;
    }
}

// ---------------------------------------------------------------------------
__global__ __launch_bounds__(256)
void bnrp_k(const float* __restrict__ s1, const float* __restrict__ stats,
            float* __restrict__ y1)
{
    __shared__ float a[CSP], bc[CSP];
    int t = threadIdx.x;
    if (t < CSP) { a[t] = stats[2*t]; bc[t] = stats[2*t+1]; }
    __syncthreads();
    int g = blockIdx.x * 256 + t;
    int b = g >> 14, pix = g & (HWSZ - 1);
    const float* sp_ = s1 + (size_t)b*CSP*HWSZ + pix;
    float* yp = y1 + (size_t)b*64*HWSZ + pix;
    float q = 0.f;
#pragma unroll 9
    for (int c = 0; c < CSP; c++) {
        float v = sp_[(size_t)c*HWSZ];
        float h = fmaf(a[c], v, bc[c]);
        float r = fmaxf(h, 0.f);
        yp[(size_t)(c+1)*HWSZ] = r;
        q = fmaf(r, r, q);
    }
    yp[0] = sqrtf(1.f + q);
}

__global__ __launch_bounds__(256)
void final_k(const float* __restrict__ s2, const float* __restrict__ sp,
             const float* __restrict__ st2, const float* __restrict__ stp,
             float* __restrict__ out)
{
    __shared__ float a2[CSP], b2s[CSP], apv[CSP], bpv[CSP];
    int t = threadIdx.x;
    if (t < CSP) {
        a2[t]  = st2[2*t]; b2s[t] = st2[2*t+1];
        apv[t] = stp[2*t]; bpv[t] = stp[2*t+1];
    }
    __syncthreads();
    int g = blockIdx.x * 256 + t;
    int b = g >> 14, pix = g & (HWSZ - 1);
    const float* p2 = s2 + (size_t)b*CSP*HWSZ + pix;
    const float* pp = sp + (size_t)b*CSP*HWSZ + pix;
    float* op = out + (size_t)b*64*HWSZ + pix;
    float q = 0.f;
#pragma unroll 9
    for (int c = 0; c < CSP; c++) {
        float v2 = p2[(size_t)c*HWSZ];
        float vp = pp[(size_t)c*HWSZ];
        float h = fmaf(a2[c], v2, b2s[c]) + fmaf(apv[c], vp, bpv[c]);
        float r = fmaxf(h, 0.f);
        op[(size_t)(c+1)*HWSZ] = r;
        q = fmaf(r, r, q);
    }
    op[0] = sqrtf(1.f + q);
}

// ---------------------------------------------------------------------------
extern "C" void kernel_launch(void* const* d_in, const int* in_sizes, int n_in,
                              void* d_out, int out_size)
{
    const float* x   = (const float*)d_in[0];
    const float* w1  = (const float*)d_in[1];
    const float* b1  = (const float*)d_in[2];
    const float* g1  = (const float*)d_in[3];
    const float* bt1 = (const float*)d_in[4];
    const float* w2  = (const float*)d_in[5];
    const float* b2  = (const float*)d_in[6];
    const float* g2  = (const float*)d_in[7];
    const float* bt2 = (const float*)d_in[8];
    const float* wp  = (const float*)d_in[9];
    const float* bp  = (const float*)d_in[10];
    const float* gp  = (const float*)d_in[11];
    const float* btp = (const float*)d_in[12];
    float* out = (float*)d_out;

    void *p_s1, *p_y1, *p_s2, *p_sp, *p_part, *p_stats;
    cudaGetSymbolAddress(&p_s1, g_s1);
    cudaGetSymbolAddress(&p_y1, g_y1);
    cudaGetSymbolAddress(&p_s2, g_s2);
    cudaGetSymbolAddress(&p_sp, g_sp);
    cudaGetSymbolAddress(&p_part, g_part);
    cudaGetSymbolAddress(&p_stats, g_stats);
    float* s1 = (float*)p_s1;
    float* y1 = (float*)p_y1;
    float* s2 = (float*)p_s2;
    float* sp = (float*)p_sp;
    float* part  = (float*)p_part;
    float* stats = (float*)p_stats;

    dim3 cg(4, 4, BB*4);
    const int ew_blocks = BB*HWSZ/256;

    conv_k<3, CIN1><<<cg, 256>>>(x, w1, b1, s1, part + 0*PART_STRIDE);
    stats_k<<<CSP, 256>>>(part + 0*PART_STRIDE, g1, bt1, stats + 0*CSP*2);
    bnrp_k<<<ew_blocks, 256>>>(s1, stats + 0*CSP*2, y1);

    conv_k<3, CIN2><<<cg, 256>>>(y1, w2, b2, s2, part + 1*PART_STRIDE);
    conv_k<1, CIN1><<<cg, 256>>>(x, wp, bp, sp, part + 2*PART_STRIDE);
    stats_k<<<CSP, 256>>>(part + 1*PART_STRIDE, g2, bt2, stats + 1*CSP*2);
    stats_k<<<CSP, 256>>>(part + 2*PART_STRIDE, gp, btp, stats + 2*CSP*2);

    final_k<<<ew_blocks, 256>>>(s2, sp, stats + 1*CSP*2, stats + 2*CSP*2, out);
}